// round 2
// baseline (speedup 1.0000x reference)
#include <cuda_runtime.h>

// Problem constants (fixed by the dataset)
#define BB 4096
#define TT 512
#define FF 64
#define HH 32

// 1 GiB scratch for the 4 gate pre-activations: [B][T][128] fp32
// (device global — allocation-free per harness rules)
__device__ float g_proj[(size_t)BB * TT * 128];

typedef unsigned long long u64;

// ---- packed fp32x2 helpers (Blackwell FFMA2, PTX-only) ----
__device__ __forceinline__ u64 pk2(float lo, float hi) {
    u64 r; asm("mov.b64 %0, {%1,%2};" : "=l"(r) : "f"(lo), "f"(hi)); return r;
}
__device__ __forceinline__ void upk2(u64 v, float &lo, float &hi) {
    asm("mov.b64 {%0,%1}, %2;" : "=f"(lo), "=f"(hi) : "l"(v));
}
__device__ __forceinline__ void fma2(u64 &acc, u64 a, u64 b) {
    asm("fma.rn.f32x2 %0, %1, %2, %0;" : "+l"(acc) : "l"(a), "l"(b));
}

// =====================================================================
// Phase 1: gate pre-activations  proj[r][n] = sum_k x[r][k] * W4t[k][n] + b4[n]
//   r = b*512 + t  (2M rows), n = gate*32 + j (128 cols), k = 0..63
// Tile: 128 rows x 128 cols per CTA, 256 threads, thread tile 8x8.
// =====================================================================
#define P1_SMEM (128*68*4 + 64*128*4 + 128*4)

__global__ void __launch_bounds__(256) proj_kernel(
    const float* __restrict__ x,
    const float* __restrict__ wf, const float* __restrict__ wfb,
    const float* __restrict__ wi, const float* __restrict__ wib,
    const float* __restrict__ wo, const float* __restrict__ wob,
    const float* __restrict__ wz, const float* __restrict__ wzb)
{
    extern __shared__ float sm[];
    float* xs = sm;                 // [128][68]  (padded rows)
    float* ws = sm + 128 * 68;      // [64][128]  W transposed, gates stacked
    float* bs = ws + 64 * 128;      // [128]
    const int tid = threadIdx.x;

    // Stage W4^T: ws[k][g*32+j] = W_g[j][k]
    for (int i = tid; i < 64 * 128; i += 256) {
        int k = i >> 7, n = i & 127, g = n >> 5, j = n & 31;
        const float* w = (g == 0) ? wf : (g == 1) ? wi : (g == 2) ? wo : wz;
        ws[i] = w[j * 64 + k];
    }
    if (tid < 128) {
        int g = tid >> 5, j = tid & 31;
        const float* bb = (g == 0) ? wfb : (g == 1) ? wib : (g == 2) ? wob : wzb;
        bs[tid] = bb[j];
    }
    // Stage x tile: 128 rows x 64 floats (coalesced float4)
    const float4* X4 = (const float4*)x;
    const size_t base = (size_t)blockIdx.x * 2048;  // float4 units
    for (int i = tid; i < 2048; i += 256) {
        float4 v = X4[base + i];
        int r = i >> 4, c = i & 15;
        *(float4*)&xs[r * 68 + c * 4] = v;
    }
    __syncthreads();

    const int tx = tid & 15, ty = tid >> 4;
    const int r0 = ty * 8, c0 = tx * 8;

    u64 acc[8][4];
    #pragma unroll
    for (int rr = 0; rr < 8; ++rr)
        #pragma unroll
        for (int p = 0; p < 4; ++p) acc[rr][p] = 0ULL;   // bit pattern = (0.f,0.f)

    #pragma unroll 4
    for (int k4 = 0; k4 < 16; ++k4) {
        float4 a4[8];
        #pragma unroll
        for (int rr = 0; rr < 8; ++rr)
            a4[rr] = *(const float4*)&xs[(r0 + rr) * 68 + k4 * 4];
        #pragma unroll
        for (int kk = 0; kk < 4; ++kk) {
            const float* wr = &ws[(k4 * 4 + kk) * 128 + c0];
            ulonglong2 b01 = *(const ulonglong2*)wr;
            ulonglong2 b23 = *(const ulonglong2*)(wr + 4);
            #pragma unroll
            for (int rr = 0; rr < 8; ++rr) {
                float av = (kk == 0) ? a4[rr].x : (kk == 1) ? a4[rr].y
                         : (kk == 2) ? a4[rr].z : a4[rr].w;
                u64 aa = pk2(av, av);
                fma2(acc[rr][0], aa, b01.x);
                fma2(acc[rr][1], aa, b01.y);
                fma2(acc[rr][2], aa, b23.x);
                fma2(acc[rr][3], aa, b23.y);
            }
        }
    }

    const size_t rowbase = (size_t)blockIdx.x * 128;
    #pragma unroll
    for (int rr = 0; rr < 8; ++rr) {
        float v[8];
        #pragma unroll
        for (int p = 0; p < 4; ++p) {
            float lo, hi; upk2(acc[rr][p], lo, hi);
            v[2 * p] = lo; v[2 * p + 1] = hi;
        }
        #pragma unroll
        for (int q = 0; q < 8; ++q) v[q] += bs[c0 + q];
        float* o = g_proj + (rowbase + r0 + rr) * 128 + c0;
        *(float4*)o       = make_float4(v[0], v[1], v[2], v[3]);
        *(float4*)(o + 4) = make_float4(v[4], v[5], v[6], v[7]);
    }
}

// =====================================================================
// Phase 2: warp-per-batch sLSTM scan. Lane j owns hidden unit j.
// R rows register-resident as f32x2 pairs; h broadcast via smem.
// =====================================================================
__global__ void __launch_bounds__(128) scan_kernel(
    const float* __restrict__ rf, const float* __restrict__ ri,
    const float* __restrict__ ro, const float* __restrict__ rz,
    const void*  __restrict__ tick, const float* __restrict__ emb,
    const float* __restrict__ fcw, const float* __restrict__ fcb,
    float* __restrict__ out)
{
    __shared__ __align__(16) float hsh[4][32];
    const int tid = threadIdx.x;
    const int w = tid >> 5, j = tid & 31;
    const int b = blockIdx.x * 4 + w;

    // Register-resident recurrent weight rows (row j of each R), packed pairs
    u64 Rf[16], Ri[16], Ro[16], Rz[16];
    {
        const u64* pf = (const u64*)(rf + j * 32);
        const u64* pi = (const u64*)(ri + j * 32);
        const u64* po = (const u64*)(ro + j * 32);
        const u64* pz = (const u64*)(rz + j * 32);
        #pragma unroll
        for (int k = 0; k < 16; ++k) {
            Rf[k] = pf[k]; Ri[k] = pi[k]; Ro[k] = po[k]; Rz[k] = pz[k];
        }
    }

    const float* gp = g_proj + (size_t)b * (TT * 128) + j;
    float h = 0.f, c = 0.f, n = 0.f;
    // prefetch t = 0
    float nxf = gp[0], nxi = gp[32], nxo = gp[64], nxz = gp[96];

    const u64* hp = (const u64*)hsh[w];

    for (int t = 0; t < TT; ++t) {
        float xf = nxf, xi = nxi, xo = nxo, xz = nxz;
        if (t < TT - 1) {
            const float* g2 = gp + (size_t)(t + 1) * 128;
            nxf = g2[0]; nxi = g2[32]; nxo = g2[64]; nxz = g2[96];
        }
        __syncwarp();
        hsh[w][j] = h;
        __syncwarp();

        u64 af = pk2(xf, 0.f), ai = pk2(xi, 0.f);
        u64 ao = pk2(xo, 0.f), az = pk2(xz, 0.f);
        #pragma unroll
        for (int k = 0; k < 16; ++k) {
            u64 hh = hp[k];                 // broadcast LDS, conflict-free
            fma2(af, Rf[k], hh);
            fma2(ai, Ri[k], hh);
            fma2(ao, Ro[k], hh);
            fma2(az, Rz[k], hh);
        }
        float lo, hi;
        upk2(af, lo, hi); float fT = lo + hi;
        upk2(ai, lo, hi); float iT = lo + hi;
        upk2(ao, lo, hi); float oT = lo + hi;
        upk2(az, lo, hi); float zT = lo + hi;

        float fh = __expf(fminf(fT, 10.f));
        float ih = __expf(fminf(iT, 10.f));
        float rden = __fdividef(1.f, fh + ih + 1e-8f);
        float f  = fh * rden;
        float ii = ih * rden;
        float o  = __fdividef(1.f, 1.f + __expf(-oT));
        float za = fabsf(zT);
        float e2 = __expf(-2.f * za);                       // in (0,1], no overflow
        float z  = copysignf(__fdividef(1.f - e2, 1.f + e2), zT);
        c = f * c + ii * z;
        n = f * n + ii;
        h = o * __fdividef(c, n + 1e-8f);
    }

    // Final head: tanh(fc_w . [h, emb[ticker]] + fc_b)
    float v = fcw[j] * h;
    // ticker_id dtype detection: int64 (x64-enabled jax) has zero high words
    const int* p32 = (const int*)tick;
    bool is64 = ((p32[1] | p32[3] | p32[5] | p32[7] |
                  p32[9] | p32[11] | p32[13] | p32[15]) == 0);
    long long id = is64 ? ((const long long*)tick)[b] : (long long)p32[b];
    if (j < 8) v += fcw[32 + j] * emb[id * 8 + j];
    #pragma unroll
    for (int off = 16; off; off >>= 1)
        v += __shfl_xor_sync(0xffffffffu, v, off);
    if (j == 0) out[b] = tanhf(v + fcb[0]);
}

// =====================================================================
extern "C" void kernel_launch(void* const* d_in, const int* in_sizes, int n_in,
                              void* d_out, int out_size) {
    const float* x   = (const float*)d_in[0];
    const void*  tid = d_in[1];
    const float* wf  = (const float*)d_in[2];
    const float* wfb = (const float*)d_in[3];
    const float* wi  = (const float*)d_in[4];
    const float* wib = (const float*)d_in[5];
    const float* wo  = (const float*)d_in[6];
    const float* wob = (const float*)d_in[7];
    const float* wz  = (const float*)d_in[8];
    const float* wzb = (const float*)d_in[9];
    const float* rf  = (const float*)d_in[10];
    const float* ri  = (const float*)d_in[11];
    const float* ro  = (const float*)d_in[12];
    const float* rz  = (const float*)d_in[13];
    const float* emb = (const float*)d_in[14];
    const float* fcw = (const float*)d_in[15];
    const float* fcb = (const float*)d_in[16];
    float* out = (float*)d_out;

    cudaFuncSetAttribute(proj_kernel,
                         cudaFuncAttributeMaxDynamicSharedMemorySize, P1_SMEM);

    proj_kernel<<<(BB * TT) / 128, 256, P1_SMEM>>>(
        x, wf, wfb, wi, wib, wo, wob, wz, wzb);
    scan_kernel<<<BB / 4, 128>>>(rf, ri, ro, rz, tid, emb, fcw, fcb, out);
}

// round 5
// speedup vs baseline: 2.4808x; 2.4808x over previous
#include <cuda_runtime.h>
#include <cuda_bf16.h>

#define BB 4096
#define TT 512

// 1 GiB scratch for gate pre-activations: [B][T][128] fp32 (g*32+j order)
__device__ float g_proj[(size_t)BB * TT * 128];

typedef unsigned long long u64;
typedef unsigned int u32;

__device__ __forceinline__ u32 smem_u32(const void* p) {
    u32 a;
    asm("{ .reg .u64 t; cvta.to.shared.u64 t, %1; cvt.u32.u64 %0, t; }"
        : "=r"(a) : "l"(p));
    return a;
}
__device__ __forceinline__ u32 swz(u32 off) { return off ^ ((off >> 3) & 0x70); }

// ---- packed fp32x2 (scan) ----
__device__ __forceinline__ u64 pk2(float lo, float hi) {
    u64 r; asm("mov.b64 %0, {%1,%2};" : "=l"(r) : "f"(lo), "f"(hi)); return r;
}
__device__ __forceinline__ void upk2(u64 v, float &lo, float &hi) {
    asm("mov.b64 {%0,%1}, %2;" : "=f"(lo), "=f"(hi) : "l"(v));
}
__device__ __forceinline__ void fma2(u64 &acc, u64 a, u64 b) {
    asm("fma.rn.f32x2 %0, %1, %2, %0;" : "+l"(acc) : "l"(a), "l"(b));
}

// ---- HMMA helpers ----
__device__ __forceinline__ void ldsm4(u32 &r0, u32 &r1, u32 &r2, u32 &r3, u32 a) {
    asm volatile("ldmatrix.sync.aligned.m8n8.x4.shared.b16 {%0,%1,%2,%3}, [%4];"
                 : "=r"(r0), "=r"(r1), "=r"(r2), "=r"(r3) : "r"(a));
}
__device__ __forceinline__ void mma16816(float* c, const u32* a, u32 b0, u32 b1) {
    asm volatile(
        "mma.sync.aligned.m16n8k16.row.col.f32.bf16.bf16.f32 "
        "{%0,%1,%2,%3}, {%4,%5,%6,%7}, {%8,%9}, {%0,%1,%2,%3};"
        : "+f"(c[0]), "+f"(c[1]), "+f"(c[2]), "+f"(c[3])
        : "r"(a[0]), "r"(a[1]), "r"(a[2]), "r"(a[3]), "r"(b0), "r"(b1));
}

// =====================================================================
// Phase 1: proj[r][n] = sum_k x[r][k]*W4[n][k] + b4[n]     (HMMA bf16-split)
// smem: [0,512) bias | [1024,66560) A 2buf x (hi16K+lo16K) | [66560) Whi | [82944) Wlo
// =====================================================================
#define PJ_SMEM 99328
#define A_OFF(buf, hl) (1024 + (buf) * 32768 + (hl) * 16384)
#define BH_OFF 66560
#define BL_OFF 82944

__global__ void __launch_bounds__(256) proj_mma(
    const float* __restrict__ x,
    const float* __restrict__ wf, const float* __restrict__ wfb,
    const float* __restrict__ wi, const float* __restrict__ wib,
    const float* __restrict__ wo, const float* __restrict__ wob,
    const float* __restrict__ wz, const float* __restrict__ wzb)
{
    extern __shared__ __align__(1024) char sm[];
    float* bs = (float*)sm;
    const int tid = threadIdx.x;
    const int wid = tid >> 5, lane = tid & 31;
    const u32 sb = smem_u32(sm);

    // ---- stage W hi/lo ([n=128 rows][k=64] bf16, 128B rows, swizzled) ----
    for (int i = tid; i < 4096; i += 256) {          // (n, k-pair)
        int n = i >> 5, kp = i & 31;
        int g = n >> 5, j = n & 31;
        const float* wp = (g == 0) ? wf : (g == 1) ? wi : (g == 2) ? wo : wz;
        float a = wp[j * 64 + kp * 2], b = wp[j * 64 + kp * 2 + 1];
        __nv_bfloat162 h = __floats2bfloat162_rn(a, b);
        float ha = __bfloat162float(h.x), hb = __bfloat162float(h.y);
        __nv_bfloat162 l = __floats2bfloat162_rn(a - ha, b - hb);
        u32 off = swz((u32)(n * 128 + kp * 4));
        *(u32*)(sm + BH_OFF + off) = *(u32*)&h;
        *(u32*)(sm + BL_OFF + off) = *(u32*)&l;
    }
    if (tid < 128) {
        int g = tid >> 5, j = tid & 31;
        const float* bb = (g == 0) ? wfb : (g == 1) ? wib : (g == 2) ? wob : wzb;
        bs[tid] = bb[j];
    }

    const size_t tile0 = (size_t)blockIdx.x * 8;

    // staging: each thread handles 8 float4 (2 halves of 4)
    auto stage_ld = [&](size_t tile, int half, float4* v) {
        const float4* X4 = (const float4*)x + tile * 2048 + half * 1024;
        #pragma unroll
        for (int q = 0; q < 4; ++q) v[q] = X4[q * 256 + tid];
    };
    auto stage_st = [&](int buf, int half, const float4* v) {
        char* ah = sm + A_OFF(buf, 0);
        char* al = sm + A_OFF(buf, 1);
        #pragma unroll
        for (int q = 0; q < 4; ++q) {
            int i = half * 1024 + q * 256 + tid;
            float4 w = v[q];
            int r = i >> 4, c4 = i & 15;
            __nv_bfloat162 h0 = __floats2bfloat162_rn(w.x, w.y);
            __nv_bfloat162 h1 = __floats2bfloat162_rn(w.z, w.w);
            float r0 = w.x - __bfloat162float(h0.x);
            float r1 = w.y - __bfloat162float(h0.y);
            float r2 = w.z - __bfloat162float(h1.x);
            float r3 = w.w - __bfloat162float(h1.y);
            __nv_bfloat162 l0 = __floats2bfloat162_rn(r0, r1);
            __nv_bfloat162 l1 = __floats2bfloat162_rn(r2, r3);
            u32 off = swz((u32)(r * 128 + c4 * 8));
            *(u64*)(ah + off) = (u64)(*(u32*)&h0) | ((u64)(*(u32*)&h1) << 32);
            *(u64*)(al + off) = (u64)(*(u32*)&l0) | ((u64)(*(u32*)&l1) << 32);
        }
    };

    float4 v[4];
    stage_ld(tile0, 0, v); stage_st(0, 0, v);
    stage_ld(tile0, 1, v); stage_st(0, 1, v);
    __syncthreads();

    const int mwarp = wid & 3, nwarp = wid >> 2;
    // ldmatrix lane address components (A and B both non-trans)
    const int arow_l = lane & 15, acol_l = (lane >> 4) * 16;
    const int brow_l = (lane & 7) + ((lane >> 4) << 3);
    const int bcol_l = ((lane >> 3) & 1) * 16;

    // one accumulation pass over K=64 (4 k-steps)
    auto pass = [&](float acc[2][8][4], u32 abase, u32 bbase) {
        #pragma unroll
        for (int s = 0; s < 4; ++s) {
            u32 a[2][4];
            #pragma unroll
            for (int mt = 0; mt < 2; ++mt) {
                int row = mwarp * 32 + mt * 16 + arow_l;
                ldsm4(a[mt][0], a[mt][1], a[mt][2], a[mt][3],
                      abase + swz((u32)(row * 128 + s * 32 + acol_l)));
            }
            u32 b[8][2];
            #pragma unroll
            for (int nb = 0; nb < 4; ++nb) {
                int row = nwarp * 64 + nb * 16 + brow_l;
                // W tile is [n][k] (k contiguous) == B column-major:
                // plain ldmatrix yields lane l -> (n=l/4, k=(l%4)*2+i), the
                // exact m16n8k16 B-fragment layout. (.trans here was the R4 bug.)
                ldsm4(b[nb * 2][0], b[nb * 2][1], b[nb * 2 + 1][0], b[nb * 2 + 1][1],
                      bbase + swz((u32)(row * 128 + s * 32 + bcol_l)));
            }
            #pragma unroll
            for (int mt = 0; mt < 2; ++mt)
                #pragma unroll
                for (int nt = 0; nt < 8; ++nt)
                    mma16816(acc[mt][nt], a[mt], b[nt][0], b[nt][1]);
        }
    };

    for (int t = 0; t < 8; ++t) {
        const int buf = t & 1;
        float acc[2][8][4];
        #pragma unroll
        for (int mt = 0; mt < 2; ++mt)
            #pragma unroll
            for (int nt = 0; nt < 8; ++nt)
                #pragma unroll
                for (int q = 0; q < 4; ++q) acc[mt][nt][q] = 0.f;

        const u32 ah = sb + A_OFF(buf, 0);
        const u32 al = sb + A_OFF(buf, 1);

        if (t < 7) stage_ld(tile0 + t + 1, 0, v);
        pass(acc, ah, sb + BH_OFF);                      // hi*hi
        if (t < 7) { stage_st(buf ^ 1, 0, v); stage_ld(tile0 + t + 1, 1, v); }
        pass(acc, al, sb + BH_OFF);                      // lo*hi
        if (t < 7) stage_st(buf ^ 1, 1, v);
        pass(acc, ah, sb + BL_OFF);                      // hi*lo

        // epilogue: +bias, direct STG.64 (32B sectors fully covered)
        const size_t rowbase = (tile0 + t) * 128 + mwarp * 32;
        const int colb = nwarp * 64;
        #pragma unroll
        for (int mt = 0; mt < 2; ++mt) {
            const size_t r0 = rowbase + mt * 16 + (lane >> 2);
            #pragma unroll
            for (int nt = 0; nt < 8; ++nt) {
                int col = colb + nt * 8 + (lane & 3) * 2;
                float b0v = bs[col], b1v = bs[col + 1];
                float2 dlo = make_float2(acc[mt][nt][0] + b0v, acc[mt][nt][1] + b1v);
                float2 dhi = make_float2(acc[mt][nt][2] + b0v, acc[mt][nt][3] + b1v);
                *(float2*)(g_proj + r0 * 128 + col)       = dlo;
                *(float2*)(g_proj + (r0 + 8) * 128 + col) = dhi;
            }
        }
        __syncthreads();
    }
}

// =====================================================================
// Phase 2: warp-per-batch sLSTM scan, 32-thread blocks, 4-deep gate prefetch.
// =====================================================================
__global__ void __launch_bounds__(32) scan_kernel(
    const float* __restrict__ rf, const float* __restrict__ ri,
    const float* __restrict__ ro, const float* __restrict__ rz,
    const void*  __restrict__ tick, const float* __restrict__ emb,
    const float* __restrict__ fcw, const float* __restrict__ fcb,
    float* __restrict__ out)
{
    __shared__ __align__(16) float hsh[32];
    const int j = threadIdx.x;
    const int b = blockIdx.x;

    u64 Rf[16], Ri[16], Ro[16], Rz[16];
    {
        const u64* pf = (const u64*)(rf + j * 32);
        const u64* pi = (const u64*)(ri + j * 32);
        const u64* po = (const u64*)(ro + j * 32);
        const u64* pz = (const u64*)(rz + j * 32);
        #pragma unroll
        for (int k = 0; k < 16; ++k) {
            Rf[k] = pf[k]; Ri[k] = pi[k]; Ro[k] = po[k]; Rz[k] = pz[k];
        }
    }

    const float* gp = g_proj + (size_t)b * (TT * 128) + j;
    float h = 0.f, c = 0.f, n = 0.f;

    // 4-deep prefetch ring (kept in regs via unroll-4)
    float pxf[4], pxi[4], pxo[4], pxz[4];
    #pragma unroll
    for (int s = 0; s < 4; ++s) {
        const float* g2 = gp + (size_t)s * 128;
        pxf[s] = g2[0]; pxi[s] = g2[32]; pxo[s] = g2[64]; pxz[s] = g2[96];
    }

    const u64* hp = (const u64*)hsh;

    #pragma unroll 4
    for (int t = 0; t < TT; ++t) {
        const int sl = t & 3;
        float xf = pxf[sl], xi = pxi[sl], xo = pxo[sl], xz = pxz[sl];
        {   // prefetch t+4 (clamped; extra reload harmless)
            int tp = (t + 4 < TT) ? (t + 4) : t;
            const float* g2 = gp + (size_t)tp * 128;
            pxf[sl] = g2[0]; pxi[sl] = g2[32]; pxo[sl] = g2[64]; pxz[sl] = g2[96];
        }
        __syncwarp();
        hsh[j] = h;
        __syncwarp();

        u64 af = pk2(xf, 0.f), ai = pk2(xi, 0.f);
        u64 ao = pk2(xo, 0.f), az = pk2(xz, 0.f);
        #pragma unroll
        for (int k = 0; k < 16; ++k) {
            u64 hh = hp[k];
            fma2(af, Rf[k], hh);
            fma2(ai, Ri[k], hh);
            fma2(ao, Ro[k], hh);
            fma2(az, Rz[k], hh);
        }
        float lo, hi;
        upk2(af, lo, hi); float fT = lo + hi;
        upk2(ai, lo, hi); float iT = lo + hi;
        upk2(ao, lo, hi); float oT = lo + hi;
        upk2(az, lo, hi); float zT = lo + hi;

        float fh = __expf(fminf(fT, 10.f));
        float ih = __expf(fminf(iT, 10.f));
        float rden = __fdividef(1.f, fh + ih + 1e-8f);
        float f  = fh * rden;
        float ii = ih * rden;
        float o  = __fdividef(1.f, 1.f + __expf(-oT));
        float za = fabsf(zT);
        float e2 = __expf(-2.f * za);
        float z  = copysignf(__fdividef(1.f - e2, 1.f + e2), zT);
        c = f * c + ii * z;
        n = f * n + ii;
        h = o * __fdividef(c, n + 1e-8f);
    }

    float v = fcw[j] * h;
    const int* p32 = (const int*)tick;
    bool is64 = ((p32[1] | p32[3] | p32[5] | p32[7] |
                  p32[9] | p32[11] | p32[13] | p32[15]) == 0);
    long long id = is64 ? ((const long long*)tick)[b] : (long long)p32[b];
    if (j < 8) v += fcw[32 + j] * emb[id * 8 + j];
    #pragma unroll
    for (int off = 16; off; off >>= 1)
        v += __shfl_xor_sync(0xffffffffu, v, off);
    if (j == 0) out[b] = tanhf(v + fcb[0]);
}

// =====================================================================
extern "C" void kernel_launch(void* const* d_in, const int* in_sizes, int n_in,
                              void* d_out, int out_size) {
    const float* x   = (const float*)d_in[0];
    const void*  tid = d_in[1];
    const float* wf  = (const float*)d_in[2];
    const float* wfb = (const float*)d_in[3];
    const float* wi  = (const float*)d_in[4];
    const float* wib = (const float*)d_in[5];
    const float* wo  = (const float*)d_in[6];
    const float* wob = (const float*)d_in[7];
    const float* wz  = (const float*)d_in[8];
    const float* wzb = (const float*)d_in[9];
    const float* rf  = (const float*)d_in[10];
    const float* ri  = (const float*)d_in[11];
    const float* ro  = (const float*)d_in[12];
    const float* rz  = (const float*)d_in[13];
    const float* emb = (const float*)d_in[14];
    const float* fcw = (const float*)d_in[15];
    const float* fcb = (const float*)d_in[16];
    float* out = (float*)d_out;

    cudaFuncSetAttribute(proj_mma,
                         cudaFuncAttributeMaxDynamicSharedMemorySize, PJ_SMEM);

    proj_mma<<<(BB * TT) / (128 * 8), 256, PJ_SMEM>>>(
        x, wf, wfb, wi, wib, wo, wob, wz, wzb);
    scan_kernel<<<BB, 32>>>(rf, ri, ro, rz, tid, emb, fcw, fcb, out);
}

// round 6
// speedup vs baseline: 2.5266x; 1.0185x over previous
#include <cuda_runtime.h>
#include <cuda_bf16.h>

#define BB 4096
#define TT 512

// 1 GiB scratch for gate pre-activations: [B][T][128] fp32 (g*32+j order)
__device__ float g_proj[(size_t)BB * TT * 128];

typedef unsigned long long u64;
typedef unsigned int u32;

__device__ __forceinline__ u32 smem_u32(const void* p) {
    u32 a;
    asm("{ .reg .u64 t; cvta.to.shared.u64 t, %1; cvt.u32.u64 %0, t; }"
        : "=r"(a) : "l"(p));
    return a;
}
__device__ __forceinline__ u32 swz(u32 off) { return off ^ ((off >> 3) & 0x70); }

// ---- packed fp32x2 (scan) ----
__device__ __forceinline__ u64 pk2(float lo, float hi) {
    u64 r; asm("mov.b64 %0, {%1,%2};" : "=l"(r) : "f"(lo), "f"(hi)); return r;
}
__device__ __forceinline__ void upk2(u64 v, float &lo, float &hi) {
    asm("mov.b64 {%0,%1}, %2;" : "=f"(lo), "=f"(hi) : "l"(v));
}
__device__ __forceinline__ void fma2(u64 &acc, u64 a, u64 b) {
    asm("fma.rn.f32x2 %0, %1, %2, %0;" : "+l"(acc) : "l"(a), "l"(b));
}

// ---- HMMA helpers ----
__device__ __forceinline__ void ldsm4(u32 &r0, u32 &r1, u32 &r2, u32 &r3, u32 a) {
    asm volatile("ldmatrix.sync.aligned.m8n8.x4.shared.b16 {%0,%1,%2,%3}, [%4];"
                 : "=r"(r0), "=r"(r1), "=r"(r2), "=r"(r3) : "r"(a));
}
__device__ __forceinline__ void mma16816(float* c, const u32* a, u32 b0, u32 b1) {
    asm volatile(
        "mma.sync.aligned.m16n8k16.row.col.f32.bf16.bf16.f32 "
        "{%0,%1,%2,%3}, {%4,%5,%6,%7}, {%8,%9}, {%0,%1,%2,%3};"
        : "+f"(c[0]), "+f"(c[1]), "+f"(c[2]), "+f"(c[3])
        : "r"(a[0]), "r"(a[1]), "r"(a[2]), "r"(a[3]), "r"(b0), "r"(b1));
}

// =====================================================================
// Phase 1: proj[r][n] = sum_k x[r][k]*W4[n][k] + b4[n]     (HMMA bf16-split)
// (unchanged from R5 — passed at ~506us)
// =====================================================================
#define PJ_SMEM 99328
#define A_OFF(buf, hl) (1024 + (buf) * 32768 + (hl) * 16384)
#define BH_OFF 66560
#define BL_OFF 82944

__global__ void __launch_bounds__(256) proj_mma(
    const float* __restrict__ x,
    const float* __restrict__ wf, const float* __restrict__ wfb,
    const float* __restrict__ wi, const float* __restrict__ wib,
    const float* __restrict__ wo, const float* __restrict__ wob,
    const float* __restrict__ wz, const float* __restrict__ wzb)
{
    extern __shared__ __align__(1024) char sm[];
    float* bs = (float*)sm;
    const int tid = threadIdx.x;
    const int wid = tid >> 5, lane = tid & 31;
    const u32 sb = smem_u32(sm);

    for (int i = tid; i < 4096; i += 256) {
        int n = i >> 5, kp = i & 31;
        int g = n >> 5, j = n & 31;
        const float* wp = (g == 0) ? wf : (g == 1) ? wi : (g == 2) ? wo : wz;
        float a = wp[j * 64 + kp * 2], b = wp[j * 64 + kp * 2 + 1];
        __nv_bfloat162 h = __floats2bfloat162_rn(a, b);
        float ha = __bfloat162float(h.x), hb = __bfloat162float(h.y);
        __nv_bfloat162 l = __floats2bfloat162_rn(a - ha, b - hb);
        u32 off = swz((u32)(n * 128 + kp * 4));
        *(u32*)(sm + BH_OFF + off) = *(u32*)&h;
        *(u32*)(sm + BL_OFF + off) = *(u32*)&l;
    }
    if (tid < 128) {
        int g = tid >> 5, j = tid & 31;
        const float* bb = (g == 0) ? wfb : (g == 1) ? wib : (g == 2) ? wob : wzb;
        bs[tid] = bb[j];
    }

    const size_t tile0 = (size_t)blockIdx.x * 8;

    auto stage_ld = [&](size_t tile, int half, float4* v) {
        const float4* X4 = (const float4*)x + tile * 2048 + half * 1024;
        #pragma unroll
        for (int q = 0; q < 4; ++q) v[q] = X4[q * 256 + tid];
    };
    auto stage_st = [&](int buf, int half, const float4* v) {
        char* ah = sm + A_OFF(buf, 0);
        char* al = sm + A_OFF(buf, 1);
        #pragma unroll
        for (int q = 0; q < 4; ++q) {
            int i = half * 1024 + q * 256 + tid;
            float4 w = v[q];
            int r = i >> 4, c4 = i & 15;
            __nv_bfloat162 h0 = __floats2bfloat162_rn(w.x, w.y);
            __nv_bfloat162 h1 = __floats2bfloat162_rn(w.z, w.w);
            float r0 = w.x - __bfloat162float(h0.x);
            float r1 = w.y - __bfloat162float(h0.y);
            float r2 = w.z - __bfloat162float(h1.x);
            float r3 = w.w - __bfloat162float(h1.y);
            __nv_bfloat162 l0 = __floats2bfloat162_rn(r0, r1);
            __nv_bfloat162 l1 = __floats2bfloat162_rn(r2, r3);
            u32 off = swz((u32)(r * 128 + c4 * 8));
            *(u64*)(ah + off) = (u64)(*(u32*)&h0) | ((u64)(*(u32*)&h1) << 32);
            *(u64*)(al + off) = (u64)(*(u32*)&l0) | ((u64)(*(u32*)&l1) << 32);
        }
    };

    float4 v[4];
    stage_ld(tile0, 0, v); stage_st(0, 0, v);
    stage_ld(tile0, 1, v); stage_st(0, 1, v);
    __syncthreads();

    const int mwarp = wid & 3, nwarp = wid >> 2;
    const int arow_l = lane & 15, acol_l = (lane >> 4) * 16;
    const int brow_l = (lane & 7) + ((lane >> 4) << 3);
    const int bcol_l = ((lane >> 3) & 1) * 16;

    auto pass = [&](float acc[2][8][4], u32 abase, u32 bbase) {
        #pragma unroll
        for (int s = 0; s < 4; ++s) {
            u32 a[2][4];
            #pragma unroll
            for (int mt = 0; mt < 2; ++mt) {
                int row = mwarp * 32 + mt * 16 + arow_l;
                ldsm4(a[mt][0], a[mt][1], a[mt][2], a[mt][3],
                      abase + swz((u32)(row * 128 + s * 32 + acol_l)));
            }
            u32 b[8][2];
            #pragma unroll
            for (int nb = 0; nb < 4; ++nb) {
                int row = nwarp * 64 + nb * 16 + brow_l;
                ldsm4(b[nb * 2][0], b[nb * 2][1], b[nb * 2 + 1][0], b[nb * 2 + 1][1],
                      bbase + swz((u32)(row * 128 + s * 32 + bcol_l)));
            }
            #pragma unroll
            for (int mt = 0; mt < 2; ++mt)
                #pragma unroll
                for (int nt = 0; nt < 8; ++nt)
                    mma16816(acc[mt][nt], a[mt], b[nt][0], b[nt][1]);
        }
    };

    for (int t = 0; t < 8; ++t) {
        const int buf = t & 1;
        float acc[2][8][4];
        #pragma unroll
        for (int mt = 0; mt < 2; ++mt)
            #pragma unroll
            for (int nt = 0; nt < 8; ++nt)
                #pragma unroll
                for (int q = 0; q < 4; ++q) acc[mt][nt][q] = 0.f;

        const u32 ah = sb + A_OFF(buf, 0);
        const u32 al = sb + A_OFF(buf, 1);

        if (t < 7) stage_ld(tile0 + t + 1, 0, v);
        pass(acc, ah, sb + BH_OFF);                      // hi*hi
        if (t < 7) { stage_st(buf ^ 1, 0, v); stage_ld(tile0 + t + 1, 1, v); }
        pass(acc, al, sb + BH_OFF);                      // lo*hi
        if (t < 7) stage_st(buf ^ 1, 1, v);
        pass(acc, ah, sb + BL_OFF);                      // hi*lo

        const size_t rowbase = (tile0 + t) * 128 + mwarp * 32;
        const int colb = nwarp * 64;
        #pragma unroll
        for (int mt = 0; mt < 2; ++mt) {
            const size_t r0 = rowbase + mt * 16 + (lane >> 2);
            #pragma unroll
            for (int nt = 0; nt < 8; ++nt) {
                int col = colb + nt * 8 + (lane & 3) * 2;
                float b0v = bs[col], b1v = bs[col + 1];
                float2 dlo = make_float2(acc[mt][nt][0] + b0v, acc[mt][nt][1] + b1v);
                float2 dhi = make_float2(acc[mt][nt][2] + b0v, acc[mt][nt][3] + b1v);
                *(float2*)(g_proj + r0 * 128 + col)       = dlo;
                *(float2*)(g_proj + (r0 + 8) * 128 + col) = dhi;
            }
        }
        __syncthreads();
    }
}

// =====================================================================
// Phase 2: sLSTM scan — 2 batches per warp (R weights shared in regs),
// double-buffered h broadcast (1 syncwarp/step), 4-deep gate prefetch.
// =====================================================================
__global__ void __launch_bounds__(64) scan_kernel(
    const float* __restrict__ rf, const float* __restrict__ ri,
    const float* __restrict__ ro, const float* __restrict__ rz,
    const void*  __restrict__ tick, const float* __restrict__ emb,
    const float* __restrict__ fcw, const float* __restrict__ fcb,
    float* __restrict__ out)
{
    __shared__ __align__(16) float hsh[2][2][2][32];   // [warp][batch][buf][lane]
    const int j = threadIdx.x & 31;
    const int w = threadIdx.x >> 5;
    const int bA = blockIdx.x * 4 + w * 2;
    const int bB = bA + 1;

    // Recurrent weight rows (row j of each R), shared across both batches
    u64 Rf[16], Ri[16], Ro[16], Rz[16];
    {
        const u64* pf = (const u64*)(rf + j * 32);
        const u64* pi = (const u64*)(ri + j * 32);
        const u64* po = (const u64*)(ro + j * 32);
        const u64* pz = (const u64*)(rz + j * 32);
        #pragma unroll
        for (int k = 0; k < 16; ++k) {
            Rf[k] = pf[k]; Ri[k] = pi[k]; Ro[k] = po[k]; Rz[k] = pz[k];
        }
    }

    const float* gpA = g_proj + (size_t)bA * (TT * 128) + j;
    const float* gpB = g_proj + (size_t)bB * (TT * 128) + j;
    float hA = 0.f, cA = 0.f, nA = 0.f;
    float hB = 0.f, cB = 0.f, nB = 0.f;

    // 4-deep prefetch rings
    float pAf[4], pAi[4], pAo[4], pAz[4];
    float pBf[4], pBi[4], pBo[4], pBz[4];
    #pragma unroll
    for (int s = 0; s < 4; ++s) {
        const float* a2 = gpA + (size_t)s * 128;
        const float* b2 = gpB + (size_t)s * 128;
        pAf[s] = a2[0]; pAi[s] = a2[32]; pAo[s] = a2[64]; pAz[s] = a2[96];
        pBf[s] = b2[0]; pBi[s] = b2[32]; pBo[s] = b2[64]; pBz[s] = b2[96];
    }

    #pragma unroll 4
    for (int t = 0; t < TT; ++t) {
        const int sl = t & 3, buf = t & 1;
        float xfA = pAf[sl], xiA = pAi[sl], xoA = pAo[sl], xzA = pAz[sl];
        float xfB = pBf[sl], xiB = pBi[sl], xoB = pBo[sl], xzB = pBz[sl];
        {   // prefetch t+4 (clamped; harmless reload at the tail)
            int tp = (t + 4 < TT) ? (t + 4) : t;
            const float* a2 = gpA + (size_t)tp * 128;
            const float* b2 = gpB + (size_t)tp * 128;
            pAf[sl] = a2[0]; pAi[sl] = a2[32]; pAo[sl] = a2[64]; pAz[sl] = a2[96];
            pBf[sl] = b2[0]; pBi[sl] = b2[32]; pBo[sl] = b2[64]; pBz[sl] = b2[96];
        }
        // double-buffered broadcast: next iter writes the other buffer, so a
        // single post-store syncwarp suffices.
        hsh[w][0][buf][j] = hA;
        hsh[w][1][buf][j] = hB;
        __syncwarp();
        const u64* hpA = (const u64*)hsh[w][0][buf];
        const u64* hpB = (const u64*)hsh[w][1][buf];

        u64 afA = pk2(xfA, 0.f), aiA = pk2(xiA, 0.f);
        u64 aoA = pk2(xoA, 0.f), azA = pk2(xzA, 0.f);
        u64 afB = pk2(xfB, 0.f), aiB = pk2(xiB, 0.f);
        u64 aoB = pk2(xoB, 0.f), azB = pk2(xzB, 0.f);
        #pragma unroll
        for (int k = 0; k < 16; ++k) {
            u64 hhA = hpA[k], hhB = hpB[k];
            fma2(afA, Rf[k], hhA);  fma2(afB, Rf[k], hhB);
            fma2(aiA, Ri[k], hhA);  fma2(aiB, Ri[k], hhB);
            fma2(aoA, Ro[k], hhA);  fma2(aoB, Ro[k], hhB);
            fma2(azA, Rz[k], hhA);  fma2(azB, Rz[k], hhB);
        }
        float lo, hi;
        upk2(afA, lo, hi); float fTA = lo + hi;
        upk2(aiA, lo, hi); float iTA = lo + hi;
        upk2(aoA, lo, hi); float oTA = lo + hi;
        upk2(azA, lo, hi); float zTA = lo + hi;
        upk2(afB, lo, hi); float fTB = lo + hi;
        upk2(aiB, lo, hi); float iTB = lo + hi;
        upk2(aoB, lo, hi); float oTB = lo + hi;
        upk2(azB, lo, hi); float zTB = lo + hi;

        // batch A epilogue
        {
            float fh = __expf(fminf(fTA, 10.f));
            float ih = __expf(fminf(iTA, 10.f));
            float rden = __fdividef(1.f, fh + ih + 1e-8f);
            float f  = fh * rden;
            float ii = ih * rden;
            float o  = __fdividef(1.f, 1.f + __expf(-oTA));
            float za = fabsf(zTA);
            float e2 = __expf(-2.f * za);
            float z  = copysignf(__fdividef(1.f - e2, 1.f + e2), zTA);
            cA = f * cA + ii * z;
            nA = f * nA + ii;
            hA = o * __fdividef(cA, nA + 1e-8f);
        }
        // batch B epilogue
        {
            float fh = __expf(fminf(fTB, 10.f));
            float ih = __expf(fminf(iTB, 10.f));
            float rden = __fdividef(1.f, fh + ih + 1e-8f);
            float f  = fh * rden;
            float ii = ih * rden;
            float o  = __fdividef(1.f, 1.f + __expf(-oTB));
            float za = fabsf(zTB);
            float e2 = __expf(-2.f * za);
            float z  = copysignf(__fdividef(1.f - e2, 1.f + e2), zTB);
            cB = f * cB + ii * z;
            nB = f * nB + ii;
            hB = o * __fdividef(cB, nB + 1e-8f);
        }
    }

    // Final head: tanh(fc_w . [h, emb[ticker]] + fc_b), both batches
    const int* p32 = (const int*)tick;
    bool is64 = ((p32[1] | p32[3] | p32[5] | p32[7] |
                  p32[9] | p32[11] | p32[13] | p32[15]) == 0);
    long long idA = is64 ? ((const long long*)tick)[bA] : (long long)p32[bA];
    long long idB = is64 ? ((const long long*)tick)[bB] : (long long)p32[bB];
    float vA = fcw[j] * hA;
    float vB = fcw[j] * hB;
    if (j < 8) {
        vA += fcw[32 + j] * emb[idA * 8 + j];
        vB += fcw[32 + j] * emb[idB * 8 + j];
    }
    #pragma unroll
    for (int off = 16; off; off >>= 1) {
        vA += __shfl_xor_sync(0xffffffffu, vA, off);
        vB += __shfl_xor_sync(0xffffffffu, vB, off);
    }
    if (j == 0) {
        out[bA] = tanhf(vA + fcb[0]);
        out[bB] = tanhf(vB + fcb[0]);
    }
}

// =====================================================================
extern "C" void kernel_launch(void* const* d_in, const int* in_sizes, int n_in,
                              void* d_out, int out_size) {
    const float* x   = (const float*)d_in[0];
    const void*  tid = d_in[1];
    const float* wf  = (const float*)d_in[2];
    const float* wfb = (const float*)d_in[3];
    const float* wi  = (const float*)d_in[4];
    const float* wib = (const float*)d_in[5];
    const float* wo  = (const float*)d_in[6];
    const float* wob = (const float*)d_in[7];
    const float* wz  = (const float*)d_in[8];
    const float* wzb = (const float*)d_in[9];
    const float* rf  = (const float*)d_in[10];
    const float* ri  = (const float*)d_in[11];
    const float* ro  = (const float*)d_in[12];
    const float* rz  = (const float*)d_in[13];
    const float* emb = (const float*)d_in[14];
    const float* fcw = (const float*)d_in[15];
    const float* fcb = (const float*)d_in[16];
    float* out = (float*)d_out;

    cudaFuncSetAttribute(proj_mma,
                         cudaFuncAttributeMaxDynamicSharedMemorySize, PJ_SMEM);

    proj_mma<<<(BB * TT) / (128 * 8), 256, PJ_SMEM>>>(
        x, wf, wfb, wi, wib, wo, wob, wz, wzb);
    scan_kernel<<<BB / 4, 64>>>(rf, ri, ro, rz, tid, emb, fcw, fcb, out);
}

// round 7
// speedup vs baseline: 2.8538x; 1.1295x over previous
#include <cuda_runtime.h>
#include <cuda_bf16.h>

#define BB 4096
#define TT 512
#define CH 8            // timesteps per chunk
#define NCH (TT / CH)   // 64 chunks

typedef unsigned long long u64;
typedef unsigned int u32;

// ---------------- smem layout ----------------
#define W_HI   0                    // W bf16-hi  [n=128][128B rows, swz]
#define W_LO   16384                // W bf16-lo
#define A_HI   32768                // x tile hi  [64 rows][128B, swz]
#define A_LO   40960                // x tile lo
#define PROJ_O 49152                // proj chunk [64 rows][136 floats]
#define PROW   136
#define HSH_O  83968                // h broadcast: 8 warps x 2 buf x 32 floats
#define BIAS_O 86016                // bias [128] floats
#define SM_TOT 86528

__device__ __forceinline__ u32 smem_u32(const void* p) {
    u32 a;
    asm("{ .reg .u64 t; cvta.to.shared.u64 t, %1; cvt.u32.u64 %0, t; }"
        : "=r"(a) : "l"(p));
    return a;
}
__device__ __forceinline__ u32 swz(u32 off) { return off ^ ((off >> 3) & 0x70); }

// ---- packed fp32x2 ----
__device__ __forceinline__ u64 pk2(float lo, float hi) {
    u64 r; asm("mov.b64 %0, {%1,%2};" : "=l"(r) : "f"(lo), "f"(hi)); return r;
}
__device__ __forceinline__ void upk2(u64 v, float &lo, float &hi) {
    asm("mov.b64 {%0,%1}, %2;" : "=f"(lo), "=f"(hi) : "l"(v));
}
__device__ __forceinline__ void fma2(u64 &acc, u64 a, u64 b) {
    asm("fma.rn.f32x2 %0, %1, %2, %0;" : "+l"(acc) : "l"(a), "l"(b));
}

// ---- HMMA ----
__device__ __forceinline__ void ldsm4(u32 &r0, u32 &r1, u32 &r2, u32 &r3, u32 a) {
    asm volatile("ldmatrix.sync.aligned.m8n8.x4.shared.b16 {%0,%1,%2,%3}, [%4];"
                 : "=r"(r0), "=r"(r1), "=r"(r2), "=r"(r3) : "r"(a));
}
__device__ __forceinline__ void mma16816(float* c, const u32* a, u32 b0, u32 b1) {
    asm volatile(
        "mma.sync.aligned.m16n8k16.row.col.f32.bf16.bf16.f32 "
        "{%0,%1,%2,%3}, {%4,%5,%6,%7}, {%8,%9}, {%0,%1,%2,%3};"
        : "+f"(c[0]), "+f"(c[1]), "+f"(c[2]), "+f"(c[3])
        : "r"(a[0]), "r"(a[1]), "r"(a[2]), "r"(a[3]), "r"(b0), "r"(b1));
}

// =====================================================================
// Fused kernel: per CTA 8 warps = 8 batches; chunked proj (HMMA, bf16
// hi/lo split, W-stationary register B-frags) feeding an in-smem sLSTM scan.
// =====================================================================
__global__ void __launch_bounds__(256, 1) fused_kernel(
    const float* __restrict__ x,
    const float* __restrict__ wf, const float* __restrict__ wfb,
    const float* __restrict__ wi, const float* __restrict__ wib,
    const float* __restrict__ wo, const float* __restrict__ wob,
    const float* __restrict__ wz, const float* __restrict__ wzb,
    const float* __restrict__ rf, const float* __restrict__ ri,
    const float* __restrict__ ro, const float* __restrict__ rz,
    const void*  __restrict__ tick, const float* __restrict__ emb,
    const float* __restrict__ fcw, const float* __restrict__ fcb,
    float* __restrict__ out)
{
    extern __shared__ __align__(1024) char sm[];
    const int tid = threadIdx.x;
    const int w = tid >> 5, lane = tid & 31;
    const u32 sb = smem_u32(sm);
    const int bg = blockIdx.x;
    const int batch = bg * 8 + w;

    // ---- stage W hi/lo ([n=128][k=64] bf16, 128B swz rows) + bias ----
    for (int i = tid; i < 4096; i += 256) {          // (n, k-pair)
        int n = i >> 5, kp = i & 31;
        int g = n >> 5, j = n & 31;
        const float* wp = (g == 0) ? wf : (g == 1) ? wi : (g == 2) ? wo : wz;
        float a = wp[j * 64 + kp * 2], b = wp[j * 64 + kp * 2 + 1];
        __nv_bfloat162 h2 = __floats2bfloat162_rn(a, b);
        float ha = __bfloat162float(h2.x), hb = __bfloat162float(h2.y);
        __nv_bfloat162 l2 = __floats2bfloat162_rn(a - ha, b - hb);
        u32 off = swz((u32)(n * 128 + kp * 4));
        *(u32*)(sm + W_HI + off) = *(u32*)&h2;
        *(u32*)(sm + W_LO + off) = *(u32*)&l2;
    }
    if (tid < 128) {
        int g = tid >> 5, j = tid & 31;
        const float* bb = (g == 0) ? wfb : (g == 1) ? wib : (g == 2) ? wob : wzb;
        ((float*)(sm + BIAS_O))[tid] = bb[j];
    }
    __syncthreads();

    // ---- W-stationary B fragments (warp w owns cols w*16..w*16+15) ----
    const int brow_l = (lane & 7) + ((lane >> 4) << 3);
    const int bcol_l = ((lane >> 3) & 1) * 16;
    u32 Bh[4][4], Bl[4][4];
    #pragma unroll
    for (int s = 0; s < 4; ++s) {
        u32 off = swz((u32)((w * 16 + brow_l) * 128 + s * 32 + bcol_l));
        ldsm4(Bh[s][0], Bh[s][1], Bh[s][2], Bh[s][3], sb + W_HI + off);
        ldsm4(Bl[s][0], Bl[s][1], Bl[s][2], Bl[s][3], sb + W_LO + off);
    }
    // bias regs for this warp's columns
    const float* bsm = (const float*)(sm + BIAS_O);
    const int cb = w * 16 + (lane & 3) * 2;
    const float bA0 = bsm[cb],     bA1 = bsm[cb + 1];
    const float bB0 = bsm[cb + 8], bB1 = bsm[cb + 9];

    // ---- recurrent weights, register-resident (row j = lane) ----
    u64 Rf[16], Ri[16], Ro[16], Rz[16];
    {
        const u64* pf = (const u64*)(rf + lane * 32);
        const u64* pi = (const u64*)(ri + lane * 32);
        const u64* po = (const u64*)(ro + lane * 32);
        const u64* pz = (const u64*)(rz + lane * 32);
        #pragma unroll
        for (int k = 0; k < 16; ++k) {
            Rf[k] = pf[k]; Ri[k] = pi[k]; Ro[k] = po[k]; Rz[k] = pz[k];
        }
    }

    // ---- x prefetch (chunk granularity, held in 16 regs) ----
    float4 xv[4];
    auto ldx = [&](int c) {
        #pragma unroll
        for (int q = 0; q < 4; ++q) {
            int idx = q * 256 + tid;
            int row = idx >> 4, c4 = idx & 15;
            size_t gi = ((size_t)(bg * 8 + (row >> 3)) * TT + c * CH + (row & 7)) * 16 + c4;
            xv[q] = ((const float4*)x)[gi];
        }
    };
    ldx(0);

    float h = 0.f, cst = 0.f, nst = 0.f;
    float* projf = (float*)(sm + PROJ_O);
    float* hshw  = (float*)(sm + HSH_O) + w * 64;   // 2 bufs x 32

    const int arow_l = lane & 15, acol_l = (lane >> 4) * 16;

    for (int ck = 0; ck < NCH; ++ck) {
        __syncthreads();                 // proj consumed, A-tile free
        // ---- stage A tile (convert fp32 -> bf16 hi/lo, swz) ----
        #pragma unroll
        for (int q = 0; q < 4; ++q) {
            int idx = q * 256 + tid;
            float4 v = xv[q];
            int row = idx >> 4, c4 = idx & 15;
            __nv_bfloat162 h0 = __floats2bfloat162_rn(v.x, v.y);
            __nv_bfloat162 h1 = __floats2bfloat162_rn(v.z, v.w);
            float r0 = v.x - __bfloat162float(h0.x);
            float r1 = v.y - __bfloat162float(h0.y);
            float r2 = v.z - __bfloat162float(h1.x);
            float r3 = v.w - __bfloat162float(h1.y);
            __nv_bfloat162 l0 = __floats2bfloat162_rn(r0, r1);
            __nv_bfloat162 l1 = __floats2bfloat162_rn(r2, r3);
            u32 off = swz((u32)(row * 128 + c4 * 8));
            *(u64*)(sm + A_HI + off) = (u64)(*(u32*)&h0) | ((u64)(*(u32*)&h1) << 32);
            *(u64*)(sm + A_LO + off) = (u64)(*(u32*)&l0) | ((u64)(*(u32*)&l1) << 32);
        }
        __syncthreads();                 // A ready

        // ---- HMMA: 64 rows x 16 cols per warp, fused 3-pass hi/lo ----
        float acc[4][2][4];
        #pragma unroll
        for (int mt = 0; mt < 4; ++mt)
            #pragma unroll
            for (int nt = 0; nt < 2; ++nt)
                #pragma unroll
                for (int q = 0; q < 4; ++q) acc[mt][nt][q] = 0.f;

        #pragma unroll
        for (int mt = 0; mt < 4; ++mt) {
            #pragma unroll
            for (int s = 0; s < 4; ++s) {
                u32 ah[4], al[4];
                u32 aoff = swz((u32)((mt * 16 + arow_l) * 128 + s * 32 + acol_l));
                ldsm4(ah[0], ah[1], ah[2], ah[3], sb + A_HI + aoff);
                ldsm4(al[0], al[1], al[2], al[3], sb + A_LO + aoff);
                #pragma unroll
                for (int nt = 0; nt < 2; ++nt) {
                    mma16816(acc[mt][nt], ah, Bh[s][nt * 2], Bh[s][nt * 2 + 1]);
                    mma16816(acc[mt][nt], al, Bh[s][nt * 2], Bh[s][nt * 2 + 1]);
                    mma16816(acc[mt][nt], ah, Bl[s][nt * 2], Bl[s][nt * 2 + 1]);
                }
            }
        }

        // prefetch next chunk's x while epilogue/scan run
        if (ck + 1 < NCH) ldx(ck + 1);

        // ---- epilogue: +bias -> proj smem (padded rows, N=2 max conflict) ----
        #pragma unroll
        for (int mt = 0; mt < 4; ++mt) {
            int r0 = mt * 16 + (lane >> 2);
            #pragma unroll
            for (int nt = 0; nt < 2; ++nt) {
                int col = w * 16 + nt * 8 + (lane & 3) * 2;
                float bx = nt ? bB0 : bA0, by = nt ? bB1 : bA1;
                *(float2*)&projf[r0 * PROW + col] =
                    make_float2(acc[mt][nt][0] + bx, acc[mt][nt][1] + by);
                *(float2*)&projf[(r0 + 8) * PROW + col] =
                    make_float2(acc[mt][nt][2] + bx, acc[mt][nt][3] + by);
            }
        }
        __syncthreads();                 // proj ready

        // ---- scan CH steps (warp w = its batch; gates from smem) ----
        const float* gp = projf + (size_t)w * CH * PROW;
        #pragma unroll
        for (int s = 0; s < CH; ++s) {
            const int buf = s & 1;
            float xf = gp[s * PROW + lane];
            float xi = gp[s * PROW + 32 + lane];
            float xo = gp[s * PROW + 64 + lane];
            float xz = gp[s * PROW + 96 + lane];

            hshw[buf * 32 + lane] = h;
            __syncwarp();
            const u64* hp = (const u64*)(hshw + buf * 32);

            u64 af = pk2(xf, 0.f), ai = pk2(xi, 0.f);
            u64 ao = pk2(xo, 0.f), az = pk2(xz, 0.f);
            #pragma unroll
            for (int k = 0; k < 16; ++k) {
                u64 hh = hp[k];
                fma2(af, Rf[k], hh);
                fma2(ai, Ri[k], hh);
                fma2(ao, Ro[k], hh);
                fma2(az, Rz[k], hh);
            }
            float lo, hi;
            upk2(af, lo, hi); float fT = lo + hi;
            upk2(ai, lo, hi); float iT = lo + hi;
            upk2(ao, lo, hi); float oT = lo + hi;
            upk2(az, lo, hi); float zT = lo + hi;

            float fh = __expf(fminf(fT, 10.f));
            float ih = __expf(fminf(iT, 10.f));
            float rden = __fdividef(1.f, fh + ih + 1e-8f);
            float f  = fh * rden;
            float ii = ih * rden;
            float o  = __fdividef(1.f, 1.f + __expf(-oT));
            float za = fabsf(zT);
            float e2 = __expf(-2.f * za);
            float z  = copysignf(__fdividef(1.f - e2, 1.f + e2), zT);
            cst = f * cst + ii * z;
            nst = f * nst + ii;
            h = o * __fdividef(cst, nst + 1e-8f);
        }
    }

    // ---- head: tanh(fc_w . [h, emb[ticker]] + fc_b) ----
    const int* p32 = (const int*)tick;
    bool is64 = ((p32[1] | p32[3] | p32[5] | p32[7] |
                  p32[9] | p32[11] | p32[13] | p32[15]) == 0);
    long long id = is64 ? ((const long long*)tick)[batch] : (long long)p32[batch];
    float v = fcw[lane] * h;
    if (lane < 8) v += fcw[32 + lane] * emb[id * 8 + lane];
    #pragma unroll
    for (int off = 16; off; off >>= 1)
        v += __shfl_xor_sync(0xffffffffu, v, off);
    if (lane == 0) out[batch] = tanhf(v + fcb[0]);
}

// =====================================================================
extern "C" void kernel_launch(void* const* d_in, const int* in_sizes, int n_in,
                              void* d_out, int out_size) {
    const float* x   = (const float*)d_in[0];
    const void*  tid = d_in[1];
    const float* wf  = (const float*)d_in[2];
    const float* wfb = (const float*)d_in[3];
    const float* wi  = (const float*)d_in[4];
    const float* wib = (const float*)d_in[5];
    const float* wo  = (const float*)d_in[6];
    const float* wob = (const float*)d_in[7];
    const float* wz  = (const float*)d_in[8];
    const float* wzb = (const float*)d_in[9];
    const float* rf  = (const float*)d_in[10];
    const float* ri  = (const float*)d_in[11];
    const float* ro  = (const float*)d_in[12];
    const float* rz  = (const float*)d_in[13];
    const float* emb = (const float*)d_in[14];
    const float* fcw = (const float*)d_in[15];
    const float* fcb = (const float*)d_in[16];
    float* out = (float*)d_out;

    cudaFuncSetAttribute(fused_kernel,
                         cudaFuncAttributeMaxDynamicSharedMemorySize, SM_TOT);

    fused_kernel<<<BB / 8, 256, SM_TOT>>>(
        x, wf, wfb, wi, wib, wo, wob, wz, wzb,
        rf, ri, ro, rz, tid, emb, fcw, fcb, out);
}

// round 8
// speedup vs baseline: 2.8869x; 1.0116x over previous
#include <cuda_runtime.h>
#include <cuda_bf16.h>

#define BB 4096
#define TT 512
#define CH 8            // timesteps per chunk
#define NCH (TT / CH)   // 64 chunks

typedef unsigned long long u64;
typedef unsigned int u32;

// ---------------- smem layout ----------------
#define W_HI   0                    // W bf16-hi  [n=128][128B rows, swz]
#define W_LO   16384                // W bf16-lo
#define A_HI   32768                // x tile hi  [64 rows][128B, swz]
#define A_LO   40960                // x tile lo
#define PROJ_O 49152                // proj chunk [64 rows][136 floats]
#define PROW   136
#define HSH_O  83968                // h broadcast: 8 warps x 2 buf x 32 floats
#define BIAS_O 86016                // bias [128] floats
#define SM_TOT 86528

__device__ __forceinline__ u32 smem_u32(const void* p) {
    u32 a;
    asm("{ .reg .u64 t; cvta.to.shared.u64 t, %1; cvt.u32.u64 %0, t; }"
        : "=r"(a) : "l"(p));
    return a;
}
__device__ __forceinline__ u32 swz(u32 off) { return off ^ ((off >> 3) & 0x70); }

// ---- packed fp32x2 ----
__device__ __forceinline__ u64 pk2(float lo, float hi) {
    u64 r; asm("mov.b64 %0, {%1,%2};" : "=l"(r) : "f"(lo), "f"(hi)); return r;
}
__device__ __forceinline__ void upk2(u64 v, float &lo, float &hi) {
    asm("mov.b64 {%0,%1}, %2;" : "=f"(lo), "=f"(hi) : "l"(v));
}
__device__ __forceinline__ void fma2(u64 &acc, u64 a, u64 b) {
    asm("fma.rn.f32x2 %0, %1, %2, %0;" : "+l"(acc) : "l"(a), "l"(b));
}

// ---- HMMA ----
__device__ __forceinline__ void ldsm4(u32 &r0, u32 &r1, u32 &r2, u32 &r3, u32 a) {
    asm volatile("ldmatrix.sync.aligned.m8n8.x4.shared.b16 {%0,%1,%2,%3}, [%4];"
                 : "=r"(r0), "=r"(r1), "=r"(r2), "=r"(r3) : "r"(a));
}
__device__ __forceinline__ void mma16816(float* c, const u32* a, u32 b0, u32 b1) {
    asm volatile(
        "mma.sync.aligned.m16n8k16.row.col.f32.bf16.bf16.f32 "
        "{%0,%1,%2,%3}, {%4,%5,%6,%7}, {%8,%9}, {%0,%1,%2,%3};"
        : "+f"(c[0]), "+f"(c[1]), "+f"(c[2]), "+f"(c[3])
        : "r"(a[0]), "r"(a[1]), "r"(a[2]), "r"(a[3]), "r"(b0), "r"(b1));
}

// =====================================================================
// Fused kernel, R8: reg-pressure fix — B frags re-loaded from smem per
// k-step (not register-persistent), m64 warp tile split into two m32
// groups with in-group epilogue (acc 32->16 regs). Target: zero spills.
// =====================================================================
__global__ void __launch_bounds__(256, 1) fused_kernel(
    const float* __restrict__ x,
    const float* __restrict__ wf, const float* __restrict__ wfb,
    const float* __restrict__ wi, const float* __restrict__ wib,
    const float* __restrict__ wo, const float* __restrict__ wob,
    const float* __restrict__ wz, const float* __restrict__ wzb,
    const float* __restrict__ rf, const float* __restrict__ ri,
    const float* __restrict__ ro, const float* __restrict__ rz,
    const void*  __restrict__ tick, const float* __restrict__ emb,
    const float* __restrict__ fcw, const float* __restrict__ fcb,
    float* __restrict__ out)
{
    extern __shared__ __align__(1024) char sm[];
    const int tid = threadIdx.x;
    const int w = tid >> 5, lane = tid & 31;
    const u32 sb = smem_u32(sm);
    const int bg = blockIdx.x;
    const int batch = bg * 8 + w;

    // ---- stage W hi/lo ([n=128][k=64] bf16, 128B swz rows) + bias ----
    for (int i = tid; i < 4096; i += 256) {          // (n, k-pair)
        int n = i >> 5, kp = i & 31;
        int g = n >> 5, j = n & 31;
        const float* wp = (g == 0) ? wf : (g == 1) ? wi : (g == 2) ? wo : wz;
        float a = wp[j * 64 + kp * 2], b = wp[j * 64 + kp * 2 + 1];
        __nv_bfloat162 h2 = __floats2bfloat162_rn(a, b);
        float ha = __bfloat162float(h2.x), hb = __bfloat162float(h2.y);
        __nv_bfloat162 l2 = __floats2bfloat162_rn(a - ha, b - hb);
        u32 off = swz((u32)(n * 128 + kp * 4));
        *(u32*)(sm + W_HI + off) = *(u32*)&h2;
        *(u32*)(sm + W_LO + off) = *(u32*)&l2;
    }
    if (tid < 128) {
        int g = tid >> 5, j = tid & 31;
        const float* bb = (g == 0) ? wfb : (g == 1) ? wib : (g == 2) ? wob : wzb;
        ((float*)(sm + BIAS_O))[tid] = bb[j];
    }

    // bias regs for this warp's columns (cols w*16 .. w*16+15)
    const int brow_l = (lane & 7) + ((lane >> 4) << 3);
    const int bcol_l = ((lane >> 3) & 1) * 16;
    __syncthreads();
    const float* bsm = (const float*)(sm + BIAS_O);
    const int cb = w * 16 + (lane & 3) * 2;
    const float bA0 = bsm[cb],     bA1 = bsm[cb + 1];
    const float bB0 = bsm[cb + 8], bB1 = bsm[cb + 9];

    // ---- recurrent weights, register-resident (row j = lane) ----
    u64 Rf[16], Ri[16], Ro[16], Rz[16];
    {
        const u64* pf = (const u64*)(rf + lane * 32);
        const u64* pi = (const u64*)(ri + lane * 32);
        const u64* po = (const u64*)(ro + lane * 32);
        const u64* pz = (const u64*)(rz + lane * 32);
        #pragma unroll
        for (int k = 0; k < 16; ++k) {
            Rf[k] = pf[k]; Ri[k] = pi[k]; Ro[k] = po[k]; Rz[k] = pz[k];
        }
    }

    // ---- x prefetch (chunk granularity, 16 regs) ----
    float4 xv[4];
    auto ldx = [&](int c) {
        #pragma unroll
        for (int q = 0; q < 4; ++q) {
            int idx = q * 256 + tid;
            int row = idx >> 4, c4 = idx & 15;
            size_t gi = ((size_t)(bg * 8 + (row >> 3)) * TT + c * CH + (row & 7)) * 16 + c4;
            xv[q] = ((const float4*)x)[gi];
        }
    };
    ldx(0);

    float h = 0.f, cst = 0.f, nst = 0.f;
    float* projf = (float*)(sm + PROJ_O);
    float* hshw  = (float*)(sm + HSH_O) + w * 64;   // 2 bufs x 32

    const int arow_l = lane & 15, acol_l = (lane >> 4) * 16;

    for (int ck = 0; ck < NCH; ++ck) {
        __syncthreads();                 // proj consumed, A-tile free
        // ---- stage A tile (convert fp32 -> bf16 hi/lo, swz) ----
        #pragma unroll
        for (int q = 0; q < 4; ++q) {
            int idx = q * 256 + tid;
            float4 v = xv[q];
            int row = idx >> 4, c4 = idx & 15;
            __nv_bfloat162 h0 = __floats2bfloat162_rn(v.x, v.y);
            __nv_bfloat162 h1 = __floats2bfloat162_rn(v.z, v.w);
            float r0 = v.x - __bfloat162float(h0.x);
            float r1 = v.y - __bfloat162float(h0.y);
            float r2 = v.z - __bfloat162float(h1.x);
            float r3 = v.w - __bfloat162float(h1.y);
            __nv_bfloat162 l0 = __floats2bfloat162_rn(r0, r1);
            __nv_bfloat162 l1 = __floats2bfloat162_rn(r2, r3);
            u32 off = swz((u32)(row * 128 + c4 * 8));
            *(u64*)(sm + A_HI + off) = (u64)(*(u32*)&h0) | ((u64)(*(u32*)&h1) << 32);
            *(u64*)(sm + A_LO + off) = (u64)(*(u32*)&l0) | ((u64)(*(u32*)&l1) << 32);
        }
        __syncthreads();                 // A ready

        // prefetch next chunk's x early (LDG latency hidden by HMMA+scan)
        if (ck + 1 < NCH) ldx(ck + 1);

        // ---- HMMA: two m32 groups x n16 per warp; B frags from smem ----
        #pragma unroll
        for (int g = 0; g < 2; ++g) {
            float acc[2][2][4];
            #pragma unroll
            for (int mt = 0; mt < 2; ++mt)
                #pragma unroll
                for (int nt = 0; nt < 2; ++nt)
                    #pragma unroll
                    for (int q = 0; q < 4; ++q) acc[mt][nt][q] = 0.f;

            #pragma unroll
            for (int s = 0; s < 4; ++s) {
                u32 bh[4], bl[4];
                u32 boff = swz((u32)((w * 16 + brow_l) * 128 + s * 32 + bcol_l));
                ldsm4(bh[0], bh[1], bh[2], bh[3], sb + W_HI + boff);
                ldsm4(bl[0], bl[1], bl[2], bl[3], sb + W_LO + boff);
                #pragma unroll
                for (int mt = 0; mt < 2; ++mt) {
                    u32 ah[4], al[4];
                    u32 aoff = swz((u32)(((g * 2 + mt) * 16 + arow_l) * 128 + s * 32 + acol_l));
                    ldsm4(ah[0], ah[1], ah[2], ah[3], sb + A_HI + aoff);
                    ldsm4(al[0], al[1], al[2], al[3], sb + A_LO + aoff);
                    #pragma unroll
                    for (int nt = 0; nt < 2; ++nt) {
                        mma16816(acc[mt][nt], ah, bh[nt * 2], bh[nt * 2 + 1]);
                        mma16816(acc[mt][nt], al, bh[nt * 2], bh[nt * 2 + 1]);
                        mma16816(acc[mt][nt], ah, bl[nt * 2], bl[nt * 2 + 1]);
                    }
                }
            }
            // in-group epilogue: +bias -> proj smem (padded rows)
            #pragma unroll
            for (int mt = 0; mt < 2; ++mt) {
                int r0 = (g * 2 + mt) * 16 + (lane >> 2);
                #pragma unroll
                for (int nt = 0; nt < 2; ++nt) {
                    int col = w * 16 + nt * 8 + (lane & 3) * 2;
                    float bx = nt ? bB0 : bA0, by = nt ? bB1 : bA1;
                    *(float2*)&projf[r0 * PROW + col] =
                        make_float2(acc[mt][nt][0] + bx, acc[mt][nt][1] + by);
                    *(float2*)&projf[(r0 + 8) * PROW + col] =
                        make_float2(acc[mt][nt][2] + bx, acc[mt][nt][3] + by);
                }
            }
        }
        __syncthreads();                 // proj ready

        // ---- scan CH steps (warp w = its batch; gates from smem) ----
        const float* gp = projf + (size_t)w * CH * PROW;
        #pragma unroll
        for (int s = 0; s < CH; ++s) {
            const int buf = s & 1;
            float xf = gp[s * PROW + lane];
            float xi = gp[s * PROW + 32 + lane];
            float xo = gp[s * PROW + 64 + lane];
            float xz = gp[s * PROW + 96 + lane];

            hshw[buf * 32 + lane] = h;
            __syncwarp();
            const u64* hp = (const u64*)(hshw + buf * 32);

            u64 af = pk2(xf, 0.f), ai = pk2(xi, 0.f);
            u64 ao = pk2(xo, 0.f), az = pk2(xz, 0.f);
            #pragma unroll
            for (int k = 0; k < 16; ++k) {
                u64 hh = hp[k];
                fma2(af, Rf[k], hh);
                fma2(ai, Ri[k], hh);
                fma2(ao, Ro[k], hh);
                fma2(az, Rz[k], hh);
            }
            float lo, hi;
            upk2(af, lo, hi); float fT = lo + hi;
            upk2(ai, lo, hi); float iT = lo + hi;
            upk2(ao, lo, hi); float oT = lo + hi;
            upk2(az, lo, hi); float zT = lo + hi;

            float fh = __expf(fminf(fT, 10.f));
            float ih = __expf(fminf(iT, 10.f));
            float rden = __fdividef(1.f, fh + ih + 1e-8f);
            float f  = fh * rden;
            float ii = ih * rden;
            float o  = __fdividef(1.f, 1.f + __expf(-oT));
            float za = fabsf(zT);
            float e2 = __expf(-2.f * za);
            float z  = copysignf(__fdividef(1.f - e2, 1.f + e2), zT);
            cst = f * cst + ii * z;
            nst = f * nst + ii;
            h = o * __fdividef(cst, nst + 1e-8f);
        }
    }

    // ---- head: tanh(fc_w . [h, emb[ticker]] + fc_b) ----
    const int* p32 = (const int*)tick;
    bool is64 = ((p32[1] | p32[3] | p32[5] | p32[7] |
                  p32[9] | p32[11] | p32[13] | p32[15]) == 0);
    long long id = is64 ? ((const long long*)tick)[batch] : (long long)p32[batch];
    float v = fcw[lane] * h;
    if (lane < 8) v += fcw[32 + lane] * emb[id * 8 + lane];
    #pragma unroll
    for (int off = 16; off; off >>= 1)
        v += __shfl_xor_sync(0xffffffffu, v, off);
    if (lane == 0) out[batch] = tanhf(v + fcb[0]);
}

// =====================================================================
extern "C" void kernel_launch(void* const* d_in, const int* in_sizes, int n_in,
                              void* d_out, int out_size) {
    const float* x   = (const float*)d_in[0];
    const void*  tid = d_in[1];
    const float* wf  = (const float*)d_in[2];
    const float* wfb = (const float*)d_in[3];
    const float* wi  = (const float*)d_in[4];
    const float* wib = (const float*)d_in[5];
    const float* wo  = (const float*)d_in[6];
    const float* wob = (const float*)d_in[7];
    const float* wz  = (const float*)d_in[8];
    const float* wzb = (const float*)d_in[9];
    const float* rf  = (const float*)d_in[10];
    const float* ri  = (const float*)d_in[11];
    const float* ro  = (const float*)d_in[12];
    const float* rz  = (const float*)d_in[13];
    const float* emb = (const float*)d_in[14];
    const float* fcw = (const float*)d_in[15];
    const float* fcb = (const float*)d_in[16];
    float* out = (float*)d_out;

    cudaFuncSetAttribute(fused_kernel,
                         cudaFuncAttributeMaxDynamicSharedMemorySize, SM_TOT);

    fused_kernel<<<BB / 8, 256, SM_TOT>>>(
        x, wf, wfb, wi, wib, wo, wob, wz, wzb,
        rf, ri, ro, rz, tid, emb, fcw, fcb, out);
}

// round 9
// speedup vs baseline: 3.5350x; 1.2245x over previous
#include <cuda_runtime.h>
#include <cuda_bf16.h>

#define BB 4096
#define TT 512
#define CH 16           // timesteps per chunk
#define NCH (TT / CH)   // 32 chunks
#define NB 4            // batches per CTA (1 per warp)

typedef unsigned long long u64;
typedef unsigned int u32;

// ---------------- smem layout (per 128-thread CTA) ----------------
#define W_HI   0                    // W bf16-hi  [n=128][128B rows, swz]
#define W_LO   16384                // W bf16-lo
#define A_HI   32768                // x tile hi  [64 rows][128B, swz]
#define A_LO   40960                // x tile lo
#define PROJ_O 49152                // proj chunk [64 rows][136 floats]
#define PROW   136
#define HSH_O  83968                // h broadcast: 4 warps x 2 buf x 32 floats
#define BIAS_O 84992                // bias [128] floats
#define SM_TOT 85504

__device__ __forceinline__ u32 smem_u32(const void* p) {
    u32 a;
    asm("{ .reg .u64 t; cvta.to.shared.u64 t, %1; cvt.u32.u64 %0, t; }"
        : "=r"(a) : "l"(p));
    return a;
}
__device__ __forceinline__ u32 swz(u32 off) { return off ^ ((off >> 3) & 0x70); }

// ---- packed fp32x2 ----
__device__ __forceinline__ u64 pk2(float lo, float hi) {
    u64 r; asm("mov.b64 %0, {%1,%2};" : "=l"(r) : "f"(lo), "f"(hi)); return r;
}
__device__ __forceinline__ void upk2(u64 v, float &lo, float &hi) {
    asm("mov.b64 {%0,%1}, %2;" : "=f"(lo), "=f"(hi) : "l"(v));
}
__device__ __forceinline__ void fma2(u64 &acc, u64 a, u64 b) {
    asm("fma.rn.f32x2 %0, %1, %2, %0;" : "+l"(acc) : "l"(a), "l"(b));
}

// ---- HMMA ----
__device__ __forceinline__ void ldsm4(u32 &r0, u32 &r1, u32 &r2, u32 &r3, u32 a) {
    asm volatile("ldmatrix.sync.aligned.m8n8.x4.shared.b16 {%0,%1,%2,%3}, [%4];"
                 : "=r"(r0), "=r"(r1), "=r"(r2), "=r"(r3) : "r"(a));
}
__device__ __forceinline__ void mma16816(float* c, const u32* a, u32 b0, u32 b1) {
    asm volatile(
        "mma.sync.aligned.m16n8k16.row.col.f32.bf16.bf16.f32 "
        "{%0,%1,%2,%3}, {%4,%5,%6,%7}, {%8,%9}, {%0,%1,%2,%3};"
        : "+f"(c[0]), "+f"(c[1]), "+f"(c[2]), "+f"(c[3])
        : "r"(a[0]), "r"(a[1]), "r"(a[2]), "r"(a[3]), "r"(b0), "r"(b1));
}

// =====================================================================
// Fused kernel, R9: 128-thread CTAs (4 warps = 4 batches), 2 CTAs/SM —
// two independent barrier domains so one CTA's scan (fma/MUFU) overlaps
// the other's HMMA/staging (tensor/LSU). CH=16 halves barrier count.
// =====================================================================
__global__ void __launch_bounds__(128, 2) fused_kernel(
    const float* __restrict__ x,
    const float* __restrict__ wf, const float* __restrict__ wfb,
    const float* __restrict__ wi, const float* __restrict__ wib,
    const float* __restrict__ wo, const float* __restrict__ wob,
    const float* __restrict__ wz, const float* __restrict__ wzb,
    const float* __restrict__ rf, const float* __restrict__ ri,
    const float* __restrict__ ro, const float* __restrict__ rz,
    const void*  __restrict__ tick, const float* __restrict__ emb,
    const float* __restrict__ fcw, const float* __restrict__ fcb,
    float* __restrict__ out)
{
    extern __shared__ __align__(1024) char sm[];
    const int tid = threadIdx.x;
    const int w = tid >> 5, lane = tid & 31;
    const u32 sb = smem_u32(sm);
    const int bg = blockIdx.x;
    const int batch = bg * NB + w;

    // ---- stage W hi/lo ([n=128][k=64] bf16, 128B swz rows) + bias ----
    for (int i = tid; i < 4096; i += 128) {          // (n, k-pair)
        int n = i >> 5, kp = i & 31;
        int g = n >> 5, j = n & 31;
        const float* wp = (g == 0) ? wf : (g == 1) ? wi : (g == 2) ? wo : wz;
        float a = wp[j * 64 + kp * 2], b = wp[j * 64 + kp * 2 + 1];
        __nv_bfloat162 h2 = __floats2bfloat162_rn(a, b);
        float ha = __bfloat162float(h2.x), hb = __bfloat162float(h2.y);
        __nv_bfloat162 l2 = __floats2bfloat162_rn(a - ha, b - hb);
        u32 off = swz((u32)(n * 128 + kp * 4));
        *(u32*)(sm + W_HI + off) = *(u32*)&h2;
        *(u32*)(sm + W_LO + off) = *(u32*)&l2;
    }
    if (tid < 128) {
        int g = tid >> 5, j = tid & 31;
        const float* bb = (g == 0) ? wfb : (g == 1) ? wib : (g == 2) ? wob : wzb;
        ((float*)(sm + BIAS_O))[tid] = bb[j];
    }
    __syncthreads();

    // bias regs: warp w owns gate cols w*32 .. w*32+31
    const float* bsm = (const float*)(sm + BIAS_O);
    float bR[4][2];
    #pragma unroll
    for (int nt = 0; nt < 4; ++nt) {
        int col = w * 32 + nt * 8 + (lane & 3) * 2;
        bR[nt][0] = bsm[col]; bR[nt][1] = bsm[col + 1];
    }

    // ---- recurrent weights, register-resident (row j = lane) ----
    u64 Rf[16], Ri[16], Ro[16], Rz[16];
    {
        const u64* pf = (const u64*)(rf + lane * 32);
        const u64* pi = (const u64*)(ri + lane * 32);
        const u64* po = (const u64*)(ro + lane * 32);
        const u64* pz = (const u64*)(rz + lane * 32);
        #pragma unroll
        for (int k = 0; k < 16; ++k) {
            Rf[k] = pf[k]; Ri[k] = pi[k]; Ro[k] = po[k]; Rz[k] = pz[k];
        }
    }

    // ---- x prefetch: 4 batches x 16 steps x 64 f = 1024 float4, 8/thread ----
    float4 xv[8];
    auto ldx = [&](int c) {
        #pragma unroll
        for (int q = 0; q < 8; ++q) {
            int idx = q * 128 + tid;
            int row = idx >> 4, c4 = idx & 15;
            size_t gi = ((size_t)(bg * NB + (row >> 4)) * TT + c * CH + (row & 15)) * 16 + c4;
            xv[q] = ((const float4*)x)[gi];
        }
    };
    ldx(0);

    float h = 0.f, cst = 0.f, nst = 0.f;
    float* projf = (float*)(sm + PROJ_O);
    float* hshw  = (float*)(sm + HSH_O) + w * 64;   // 2 bufs x 32

    const int arow_l = lane & 15, acol_l = (lane >> 4) * 16;
    const int brow_l = (lane & 7) + ((lane >> 4) << 3);
    const int bcol_l = ((lane >> 3) & 1) * 16;

    for (int ck = 0; ck < NCH; ++ck) {
        __syncthreads();                 // prev proj consumed, A-tile free
        // ---- stage A tile: 64 rows (batch*16+step) x 64k, bf16 hi/lo swz ----
        #pragma unroll
        for (int q = 0; q < 8; ++q) {
            int idx = q * 128 + tid;
            float4 v = xv[q];
            int row = idx >> 4, c4 = idx & 15;
            __nv_bfloat162 h0 = __floats2bfloat162_rn(v.x, v.y);
            __nv_bfloat162 h1 = __floats2bfloat162_rn(v.z, v.w);
            float r0 = v.x - __bfloat162float(h0.x);
            float r1 = v.y - __bfloat162float(h0.y);
            float r2 = v.z - __bfloat162float(h1.x);
            float r3 = v.w - __bfloat162float(h1.y);
            __nv_bfloat162 l0 = __floats2bfloat162_rn(r0, r1);
            __nv_bfloat162 l1 = __floats2bfloat162_rn(r2, r3);
            u32 off = swz((u32)(row * 128 + c4 * 8));
            *(u64*)(sm + A_HI + off) = (u64)(*(u32*)&h0) | ((u64)(*(u32*)&h1) << 32);
            *(u64*)(sm + A_LO + off) = (u64)(*(u32*)&l0) | ((u64)(*(u32*)&l1) << 32);
        }
        __syncthreads();                 // A ready

        if (ck + 1 < NCH) ldx(ck + 1);   // hide next x LDG under HMMA+scan

        // ---- HMMA: warp w -> cols w*32..+31; rows in two m32 groups ----
        #pragma unroll
        for (int g = 0; g < 2; ++g) {
            float acc[2][4][4];
            #pragma unroll
            for (int mt = 0; mt < 2; ++mt)
                #pragma unroll
                for (int nt = 0; nt < 4; ++nt)
                    #pragma unroll
                    for (int q = 0; q < 4; ++q) acc[mt][nt][q] = 0.f;

            #pragma unroll
            for (int s = 0; s < 4; ++s) {
                u32 bh[2][4], bl[2][4];
                #pragma unroll
                for (int np = 0; np < 2; ++np) {
                    u32 boff = swz((u32)((w * 32 + np * 16 + brow_l) * 128 + s * 32 + bcol_l));
                    ldsm4(bh[np][0], bh[np][1], bh[np][2], bh[np][3], sb + W_HI + boff);
                    ldsm4(bl[np][0], bl[np][1], bl[np][2], bl[np][3], sb + W_LO + boff);
                }
                #pragma unroll
                for (int mt = 0; mt < 2; ++mt) {
                    u32 ah[4], al[4];
                    u32 aoff = swz((u32)((g * 32 + mt * 16 + arow_l) * 128 + s * 32 + acol_l));
                    ldsm4(ah[0], ah[1], ah[2], ah[3], sb + A_HI + aoff);
                    ldsm4(al[0], al[1], al[2], al[3], sb + A_LO + aoff);
                    #pragma unroll
                    for (int np = 0; np < 2; ++np)
                        #pragma unroll
                        for (int nh = 0; nh < 2; ++nh) {
                            float* a5 = acc[mt][np * 2 + nh];
                            mma16816(a5, ah, bh[np][nh * 2], bh[np][nh * 2 + 1]);
                            mma16816(a5, al, bh[np][nh * 2], bh[np][nh * 2 + 1]);
                            mma16816(a5, ah, bl[np][nh * 2], bl[np][nh * 2 + 1]);
                        }
                }
            }
            // in-group epilogue: +bias -> proj smem (padded rows)
            #pragma unroll
            for (int mt = 0; mt < 2; ++mt) {
                int r0 = g * 32 + mt * 16 + (lane >> 2);
                #pragma unroll
                for (int nt = 0; nt < 4; ++nt) {
                    int col = w * 32 + nt * 8 + (lane & 3) * 2;
                    *(float2*)&projf[r0 * PROW + col] =
                        make_float2(acc[mt][nt][0] + bR[nt][0], acc[mt][nt][1] + bR[nt][1]);
                    *(float2*)&projf[(r0 + 8) * PROW + col] =
                        make_float2(acc[mt][nt][2] + bR[nt][0], acc[mt][nt][3] + bR[nt][1]);
                }
            }
        }
        __syncthreads();                 // proj ready

        // ---- scan CH steps (warp w = its batch; gates from smem) ----
        const float* gp = projf + (size_t)w * CH * PROW;
        #pragma unroll
        for (int s = 0; s < CH; ++s) {
            const int buf = s & 1;
            float xf = gp[s * PROW + lane];
            float xi = gp[s * PROW + 32 + lane];
            float xo = gp[s * PROW + 64 + lane];
            float xz = gp[s * PROW + 96 + lane];

            hshw[buf * 32 + lane] = h;
            __syncwarp();
            const u64* hp = (const u64*)(hshw + buf * 32);

            u64 af = pk2(xf, 0.f), ai = pk2(xi, 0.f);
            u64 ao = pk2(xo, 0.f), az = pk2(xz, 0.f);
            #pragma unroll
            for (int k = 0; k < 16; ++k) {
                u64 hh = hp[k];
                fma2(af, Rf[k], hh);
                fma2(ai, Ri[k], hh);
                fma2(ao, Ro[k], hh);
                fma2(az, Rz[k], hh);
            }
            float lo, hi;
            upk2(af, lo, hi); float fT = lo + hi;
            upk2(ai, lo, hi); float iT = lo + hi;
            upk2(ao, lo, hi); float oT = lo + hi;
            upk2(az, lo, hi); float zT = lo + hi;

            float fh = __expf(fminf(fT, 10.f));
            float ih = __expf(fminf(iT, 10.f));
            float rden = __fdividef(1.f, fh + ih + 1e-8f);
            float f  = fh * rden;
            float ii = ih * rden;
            float o  = __fdividef(1.f, 1.f + __expf(-oT));
            float za = fabsf(zT);
            float e2 = __expf(-2.f * za);
            float z  = copysignf(__fdividef(1.f - e2, 1.f + e2), zT);
            cst = f * cst + ii * z;
            nst = f * nst + ii;
            h = o * __fdividef(cst, nst + 1e-8f);
        }
    }

    // ---- head: tanh(fc_w . [h, emb[ticker]] + fc_b) ----
    const int* p32 = (const int*)tick;
    bool is64 = ((p32[1] | p32[3] | p32[5] | p32[7] |
                  p32[9] | p32[11] | p32[13] | p32[15]) == 0);
    long long id = is64 ? ((const long long*)tick)[batch] : (long long)p32[batch];
    float v = fcw[lane] * h;
    if (lane < 8) v += fcw[32 + lane] * emb[id * 8 + lane];
    #pragma unroll
    for (int off = 16; off; off >>= 1)
        v += __shfl_xor_sync(0xffffffffu, v, off);
    if (lane == 0) out[batch] = tanhf(v + fcb[0]);
}

// =====================================================================
extern "C" void kernel_launch(void* const* d_in, const int* in_sizes, int n_in,
                              void* d_out, int out_size) {
    const float* x   = (const float*)d_in[0];
    const void*  tid = d_in[1];
    const float* wf  = (const float*)d_in[2];
    const float* wfb = (const float*)d_in[3];
    const float* wi  = (const float*)d_in[4];
    const float* wib = (const float*)d_in[5];
    const float* wo  = (const float*)d_in[6];
    const float* wob = (const float*)d_in[7];
    const float* wz  = (const float*)d_in[8];
    const float* wzb = (const float*)d_in[9];
    const float* rf  = (const float*)d_in[10];
    const float* ri  = (const float*)d_in[11];
    const float* ro  = (const float*)d_in[12];
    const float* rz  = (const float*)d_in[13];
    const float* emb = (const float*)d_in[14];
    const float* fcw = (const float*)d_in[15];
    const float* fcb = (const float*)d_in[16];
    float* out = (float*)d_out;

    cudaFuncSetAttribute(fused_kernel,
                         cudaFuncAttributeMaxDynamicSharedMemorySize, SM_TOT);

    fused_kernel<<<BB / NB, 128, SM_TOT>>>(
        x, wf, wfb, wi, wib, wo, wob, wz, wzb,
        rf, ri, ro, rz, tid, emb, fcw, fcb, out);
}